// round 4
// baseline (speedup 1.0000x reference)
#include <cuda_runtime.h>
#include <math.h>

// EMD approxmatch (Fan et al.) on GB300 — round 4.
// Morton-sorted points + hierarchical bbox pruning (tile/chunk) + arg-vote,
// packed f32x2 math, exact level-0 sweep. B=4, N=4096.

#define EMD_EPS 1e-9f
#define NB 4
#define MAXBN (NB * 4096)
#define TILE 1024
#define RPB 16   // rows per block: 4 warps x 4 rows

typedef unsigned long long u64;

__device__ float4 g_p1[MAXBN];   // sorted (x,y,z,|p|^2) xyz1
__device__ float4 g_p2[MAXBN];   // sorted (x,y,z,|p|^2) xyz2
__device__ float  g_rL[MAXBN];
__device__ float  g_rR[MAXBN];
__device__ float  g_lgL[MAXBN];  // log2(ratioL)  (raw ratioL during level-0 sweep)
__device__ float  g_lgR[MAXBN];  // log2(ratioR)  (raw ratioR during level-0 sweep)
__device__ float  g_cost;
__device__ float4 g_cb[2][NB * 64 * 2];  // chunk (64-pt) bboxes: [(b*64+c)*2 + {lo,hi}]
__device__ float4 g_tb[2][NB * 4 * 2];   // tile (1024-pt) bboxes

__device__ __forceinline__ float ex2f(float x) {
    float y; asm("ex2.approx.ftz.f32 %0, %1;" : "=f"(y) : "f"(x)); return y;
}
__device__ __forceinline__ float lg2f(float x) {
    float y; asm("lg2.approx.ftz.f32 %0, %1;" : "=f"(y) : "f"(x)); return y;
}
__device__ __forceinline__ float sqrtf_apx(float x) {
    float y; asm("sqrt.approx.ftz.f32 %0, %1;" : "=f"(y) : "f"(x)); return y;
}
__device__ __forceinline__ u64 pk2(float a, float b) {
    u64 r; asm("mov.b64 %0, {%1, %2};" : "=l"(r) : "f"(a), "f"(b)); return r;
}
__device__ __forceinline__ void upk2(float& a, float& b, u64 v) {
    asm("mov.b64 {%0, %1}, %2;" : "=f"(a), "=f"(b) : "l"(v));
}
__device__ __forceinline__ u64 f2fma(u64 a, u64 b, u64 c) {
    u64 d; asm("fma.rn.f32x2 %0, %1, %2, %3;" : "=l"(d) : "l"(a), "l"(b), "l"(c)); return d;
}
__device__ __forceinline__ u64 f2add(u64 a, u64 b) {
    u64 d; asm("add.rn.f32x2 %0, %1, %2;" : "=l"(d) : "l"(a), "l"(b)); return d;
}

#define UF_TH (-125.0f)

__device__ __forceinline__ unsigned mort1(unsigned v) {
    return (v & 1u) | ((v & 2u) << 2) | ((v & 4u) << 4);
}

// Counting sort by Morton cell id (8^3 cells over [-4,4]^3). grid (B,2), block 512.
__global__ void sort_kernel(const float* __restrict__ x1, const float* __restrict__ x2,
                            float multiL, float multiR, int N) {
    __shared__ unsigned hist[512];
    __shared__ unsigned scan[512];
    __shared__ unsigned offs[512];
    const int b = blockIdx.x, side = blockIdx.y, t = threadIdx.x;
    const float* px = (side ? x2 : x1) + (size_t)b * 3 * N;
    hist[t] = 0;
    __syncthreads();
    for (int i = t; i < N; i += 512) {
        float a = px[i], c = px[i + N], d = px[i + 2 * N];
        unsigned cx = (unsigned)min(7, max(0, (int)floorf(a + 4.0f)));
        unsigned cy = (unsigned)min(7, max(0, (int)floorf(c + 4.0f)));
        unsigned cz = (unsigned)min(7, max(0, (int)floorf(d + 4.0f)));
        unsigned cell = mort1(cx) | (mort1(cy) << 1) | (mort1(cz) << 2);
        atomicAdd(&hist[cell], 1u);
    }
    __syncthreads();
    scan[t] = hist[t];
    __syncthreads();
    for (int o = 1; o < 512; o <<= 1) {
        unsigned add = (t >= o) ? scan[t - o] : 0u;
        __syncthreads();
        scan[t] += add;
        __syncthreads();
    }
    offs[t] = scan[t] - hist[t];
    __syncthreads();
    for (int i = t; i < N; i += 512) {
        float a = px[i], c = px[i + N], d = px[i + 2 * N];
        unsigned cx = (unsigned)min(7, max(0, (int)floorf(a + 4.0f)));
        unsigned cy = (unsigned)min(7, max(0, (int)floorf(c + 4.0f)));
        unsigned cz = (unsigned)min(7, max(0, (int)floorf(d + 4.0f)));
        unsigned cell = mort1(cx) | (mort1(cy) << 1) | (mort1(cz) << 2);
        unsigned pos = atomicAdd(&offs[cell], 1u);
        int idx = b * N + (int)pos;
        float4 v = make_float4(a, c, d, a * a + c * c + d * d);
        if (side == 0) { g_p1[idx] = v; g_rL[idx] = multiL; }
        else           { g_p2[idx] = v; g_rR[idx] = multiR; }
    }
    if (b == 0 && side == 0 && t == 0) g_cost = 0.0f;
}

// Chunk (64-pt) and tile (1024-pt) bboxes from sorted arrays. grid (B,2), block 512.
__global__ void bbox_kernel(int N) {
    __shared__ float4 slo[64], shi[64];
    const int b = blockIdx.x, side = blockIdx.y, t = threadIdx.x;
    const int warp = t >> 5, lane = t & 31;
    const float4* P = side ? g_p2 : g_p1;
    float4* CB = g_cb[side];
    float4* TB = g_tb[side];
    for (int c = warp; c < 64; c += 16) {
        int j = b * N + c * 64 + lane;
        float4 p0 = P[j], p1 = P[j + 32];
        float lx = fminf(p0.x, p1.x), hx = fmaxf(p0.x, p1.x);
        float ly = fminf(p0.y, p1.y), hy = fmaxf(p0.y, p1.y);
        float lz = fminf(p0.z, p1.z), hz = fmaxf(p0.z, p1.z);
#pragma unroll
        for (int o = 16; o; o >>= 1) {
            lx = fminf(lx, __shfl_xor_sync(0xffffffffu, lx, o));
            hx = fmaxf(hx, __shfl_xor_sync(0xffffffffu, hx, o));
            ly = fminf(ly, __shfl_xor_sync(0xffffffffu, ly, o));
            hy = fmaxf(hy, __shfl_xor_sync(0xffffffffu, hy, o));
            lz = fminf(lz, __shfl_xor_sync(0xffffffffu, lz, o));
            hz = fmaxf(hz, __shfl_xor_sync(0xffffffffu, hz, o));
        }
        if (lane == 0) {
            float4 lo = make_float4(lx, ly, lz, 0.0f);
            float4 hi = make_float4(hx, hy, hz, 0.0f);
            slo[c] = lo; shi[c] = hi;
            CB[(b * 64 + c) * 2]     = lo;
            CB[(b * 64 + c) * 2 + 1] = hi;
        }
    }
    __syncthreads();
    if (t < 4) {
        float4 lo = slo[t * 16], hi = shi[t * 16];
        for (int k = 1; k < 16; k++) {
            float4 l2 = slo[t * 16 + k], h2 = shi[t * 16 + k];
            lo.x = fminf(lo.x, l2.x); lo.y = fminf(lo.y, l2.y); lo.z = fminf(lo.z, l2.z);
            hi.x = fmaxf(hi.x, h2.x); hi.y = fmaxf(hi.y, h2.y); hi.z = fmaxf(hi.z, h2.z);
        }
        TB[(b * 4 + t) * 2]     = lo;
        TB[(b * 4 + t) * 2 + 1] = hi;
    }
}

// MODE 1: rows = x1, cols = x2, fold_j = log2(remainR_j); epilogue writes lgL.
// MODE 2: rows = x2, cols = x1, fold_j = lgL_j;           epilogue updates remainR, writes lgR.
template <int MODE, bool SPARSE>
__global__ void __launch_bounds__(128, 6) pass12_kernel(float klg, float cut2, int N) {
    __shared__ ulonglong2 s_xy[TILE / 2];
    __shared__ ulonglong2 s_zf[TILE / 2];
    __shared__ float s_wb[4][6];
    const int b = blockIdx.y, base = b * N;
    const int t = threadIdx.x, warp = t >> 5, lane = t & 31;
    const int r0 = blockIdx.x * RPB + warp * 4;

    const float4* P  = (MODE == 1) ? g_p1 : g_p2;
    const float4* Q  = (MODE == 1) ? g_p2 : g_p1;
    const float4* CB = (MODE == 1) ? g_cb[1] : g_cb[0];
    const float4* TB = (MODE == 1) ? g_tb[1] : g_tb[0];

    u64 rx[4], ry[4], rz[4], rw[4], acc[4];
    float wlx, wly, wlz, whx, why, whz;
    {
        float4 A[4];
#pragma unroll
        for (int r = 0; r < 4; r++) A[r] = P[base + r0 + r];
        wlx = fminf(fminf(A[0].x, A[1].x), fminf(A[2].x, A[3].x));
        whx = fmaxf(fmaxf(A[0].x, A[1].x), fmaxf(A[2].x, A[3].x));
        wly = fminf(fminf(A[0].y, A[1].y), fminf(A[2].y, A[3].y));
        why = fmaxf(fmaxf(A[0].y, A[1].y), fmaxf(A[2].y, A[3].y));
        wlz = fminf(fminf(A[0].z, A[1].z), fminf(A[2].z, A[3].z));
        whz = fmaxf(fmaxf(A[0].z, A[1].z), fmaxf(A[2].z, A[3].z));
        if (SPARSE && lane == 0) {
            s_wb[warp][0] = wlx; s_wb[warp][1] = wly; s_wb[warp][2] = wlz;
            s_wb[warp][3] = whx; s_wb[warp][4] = why; s_wb[warp][5] = whz;
        }
#pragma unroll
        for (int r = 0; r < 4; r++) {
            float kx = klg * -2.0f * A[r].x, ky = klg * -2.0f * A[r].y, kz = klg * -2.0f * A[r].z;
            float kw = klg * A[r].w;
            rx[r] = pk2(kx, kx); ry[r] = pk2(ky, ky); rz[r] = pk2(kz, kz); rw[r] = pk2(kw, kw);
            acc[r] = 0ull;
        }
    }
    float blx = 0, bly = 0, blz = 0, bhx = 0, bhy = 0, bhz = 0;
    if (SPARSE) {
        __syncthreads();
        blx = fminf(fminf(s_wb[0][0], s_wb[1][0]), fminf(s_wb[2][0], s_wb[3][0]));
        bly = fminf(fminf(s_wb[0][1], s_wb[1][1]), fminf(s_wb[2][1], s_wb[3][1]));
        blz = fminf(fminf(s_wb[0][2], s_wb[1][2]), fminf(s_wb[2][2], s_wb[3][2]));
        bhx = fmaxf(fmaxf(s_wb[0][3], s_wb[1][3]), fmaxf(s_wb[2][3], s_wb[3][3]));
        bhy = fmaxf(fmaxf(s_wb[0][4], s_wb[1][4]), fmaxf(s_wb[2][4], s_wb[3][4]));
        bhz = fmaxf(fmaxf(s_wb[0][5], s_wb[1][5]), fmaxf(s_wb[2][5], s_wb[3][5]));
    }

    for (int c = 0; c < N; c += TILE) {
        if (SPARSE) {
            int ti = (b * (N / TILE) + (c / TILE)) * 2;
            float4 tlo = TB[ti], thi = TB[ti + 1];
            float gx = fmaxf(0.0f, fmaxf(tlo.x - bhx, blx - thi.x));
            float gy = fmaxf(0.0f, fmaxf(tlo.y - bhy, bly - thi.y));
            float gz = fmaxf(0.0f, fmaxf(tlo.z - bhz, blz - thi.z));
            if (gx * gx + gy * gy + gz * gz > cut2) continue;   // block-uniform
        }
#pragma unroll
        for (int k = 0; k < TILE / 256; k++) {
            int p = t + k * 128;
            int j = base + c + 2 * p;
            float4 q0 = Q[j], q1 = Q[j + 1];
            float f0, f1;
            if (MODE == 1) { f0 = lg2f(g_rR[j]); f1 = lg2f(g_rR[j + 1]); }
            else           { f0 = g_lgL[j];      f1 = g_lgL[j + 1]; }
            f0 = fmaf(klg, q0.w, f0);
            f1 = fmaf(klg, q1.w, f1);
            ulonglong2 xy; xy.x = pk2(q0.x, q1.x); xy.y = pk2(q0.y, q1.y);
            ulonglong2 zf; zf.x = pk2(q0.z, q1.z); zf.y = pk2(f0, f1);
            s_xy[p] = xy; s_zf[p] = zf;
        }
        __syncthreads();
#pragma unroll 4
        for (int it = 0; it < TILE / 64; it++) {
            if (SPARSE) {
                int ci = (b * 64 + (c >> 6) + it) * 2;
                float4 clo = __ldg(&CB[ci]), chi = __ldg(&CB[ci + 1]);
                float gx = fmaxf(0.0f, fmaxf(clo.x - whx, wlx - chi.x));
                float gy = fmaxf(0.0f, fmaxf(clo.y - why, wly - chi.y));
                float gz = fmaxf(0.0f, fmaxf(clo.z - whz, wlz - chi.z));
                if (gx * gx + gy * gy + gz * gz > cut2) continue;   // warp-uniform
            }
            int p = it * 32 + lane;
            ulonglong2 xy = s_xy[p];
            ulonglong2 zf = s_zf[p];
            u64 a0 = f2fma(rz[0], zf.x, f2fma(ry[0], xy.y, f2fma(rx[0], xy.x, f2add(zf.y, rw[0]))));
            u64 a1 = f2fma(rz[1], zf.x, f2fma(ry[1], xy.y, f2fma(rx[1], xy.x, f2add(zf.y, rw[1]))));
            u64 a2 = f2fma(rz[2], zf.x, f2fma(ry[2], xy.y, f2fma(rx[2], xy.x, f2add(zf.y, rw[2]))));
            u64 a3 = f2fma(rz[3], zf.x, f2fma(ry[3], xy.y, f2fma(rx[3], xy.x, f2add(zf.y, rw[3]))));
            float e0, e1, e2, e3, e4, e5, e6, e7;
            upk2(e0, e1, a0); upk2(e2, e3, a1); upk2(e4, e5, a2); upk2(e6, e7, a3);
            if (SPARSE) {
                float m0 = fmaxf(fmaxf(e0, e1), fmaxf(e2, e3));
                float m1 = fmaxf(fmaxf(e4, e5), fmaxf(e6, e7));
                if (__all_sync(0xffffffffu, fmaxf(m0, m1) < UF_TH)) continue;
            }
            acc[0] = f2add(acc[0], pk2(ex2f(e0), ex2f(e1)));
            acc[1] = f2add(acc[1], pk2(ex2f(e2), ex2f(e3)));
            acc[2] = f2add(acc[2], pk2(ex2f(e4), ex2f(e5)));
            acc[3] = f2add(acc[3], pk2(ex2f(e6), ex2f(e7)));
        }
        __syncthreads();
    }

#pragma unroll
    for (int off = 16; off; off >>= 1) {
#pragma unroll
        for (int r = 0; r < 4; r++)
            acc[r] = f2add(acc[r], __shfl_down_sync(0xffffffffu, acc[r], off));
    }
    if (lane == 0) {
#pragma unroll
        for (int r = 0; r < 4; r++) {
            float lo, hi; upk2(lo, hi, acc[r]);
            float a = lo + hi;
            int idx = base + r0 + r;
            if (MODE == 1) {
                g_lgL[idx] = lg2f(g_rL[idx] / (EMD_EPS + a));
            } else {
                float rr   = g_rR[idx];
                float sumr = rr * a;
                float cons = fminf(rr / (sumr + EMD_EPS), 1.0f);
                g_lgR[idx] = lg2f(cons * rr);
                g_rR[idx]  = fmaxf(0.0f, rr - sumr);
            }
        }
    }
}

template <bool SPARSE>
__global__ void __launch_bounds__(128, 6) pass3_kernel(float klg, float cut2, int N) {
    __shared__ ulonglong2 s_xy[TILE / 2];
    __shared__ ulonglong2 s_zw[TILE / 2];
    __shared__ u64        s_lq[TILE / 2];
    __shared__ float s_wb[4][6];
    const int b = blockIdx.y, base = b * N;
    const int t = threadIdx.x, warp = t >> 5, lane = t & 31;
    const int r0 = blockIdx.x * RPB + warp * 4;

    u64 rx[4], ry[4], rz[4], rw[4], wa[4], cs[4];
    float lgL[4];
    float wlx, wly, wlz, whx, why, whz;
    {
        float4 A[4];
#pragma unroll
        for (int r = 0; r < 4; r++) A[r] = g_p1[base + r0 + r];
        wlx = fminf(fminf(A[0].x, A[1].x), fminf(A[2].x, A[3].x));
        whx = fmaxf(fmaxf(A[0].x, A[1].x), fmaxf(A[2].x, A[3].x));
        wly = fminf(fminf(A[0].y, A[1].y), fminf(A[2].y, A[3].y));
        why = fmaxf(fmaxf(A[0].y, A[1].y), fmaxf(A[2].y, A[3].y));
        wlz = fminf(fminf(A[0].z, A[1].z), fminf(A[2].z, A[3].z));
        whz = fmaxf(fmaxf(A[0].z, A[1].z), fmaxf(A[2].z, A[3].z));
        if (SPARSE && lane == 0) {
            s_wb[warp][0] = wlx; s_wb[warp][1] = wly; s_wb[warp][2] = wlz;
            s_wb[warp][3] = whx; s_wb[warp][4] = why; s_wb[warp][5] = whz;
        }
#pragma unroll
        for (int r = 0; r < 4; r++) {
            rx[r] = pk2(-2.0f * A[r].x, -2.0f * A[r].x);
            ry[r] = pk2(-2.0f * A[r].y, -2.0f * A[r].y);
            rz[r] = pk2(-2.0f * A[r].z, -2.0f * A[r].z);
            rw[r] = pk2(A[r].w, A[r].w);
            lgL[r] = g_lgL[base + r0 + r];
            wa[r] = 0ull; cs[r] = 0ull;
        }
    }
    float blx = 0, bly = 0, blz = 0, bhx = 0, bhy = 0, bhz = 0;
    if (SPARSE) {
        __syncthreads();
        blx = fminf(fminf(s_wb[0][0], s_wb[1][0]), fminf(s_wb[2][0], s_wb[3][0]));
        bly = fminf(fminf(s_wb[0][1], s_wb[1][1]), fminf(s_wb[2][1], s_wb[3][1]));
        blz = fminf(fminf(s_wb[0][2], s_wb[1][2]), fminf(s_wb[2][2], s_wb[3][2]));
        bhx = fmaxf(fmaxf(s_wb[0][3], s_wb[1][3]), fmaxf(s_wb[2][3], s_wb[3][3]));
        bhy = fmaxf(fmaxf(s_wb[0][4], s_wb[1][4]), fmaxf(s_wb[2][4], s_wb[3][4]));
        bhz = fmaxf(fmaxf(s_wb[0][5], s_wb[1][5]), fmaxf(s_wb[2][5], s_wb[3][5]));
    }
    const u64 klg2 = pk2(klg, klg);

    for (int c = 0; c < N; c += TILE) {
        if (SPARSE) {
            int ti = (b * (N / TILE) + (c / TILE)) * 2;
            float4 tlo = g_tb[1][ti], thi = g_tb[1][ti + 1];
            float gx = fmaxf(0.0f, fmaxf(tlo.x - bhx, blx - thi.x));
            float gy = fmaxf(0.0f, fmaxf(tlo.y - bhy, bly - thi.y));
            float gz = fmaxf(0.0f, fmaxf(tlo.z - bhz, blz - thi.z));
            if (gx * gx + gy * gy + gz * gz > cut2) continue;
        }
#pragma unroll
        for (int k = 0; k < TILE / 256; k++) {
            int p = t + k * 128;
            int j = base + c + 2 * p;
            float4 q0 = g_p2[j], q1 = g_p2[j + 1];
            ulonglong2 xy; xy.x = pk2(q0.x, q1.x); xy.y = pk2(q0.y, q1.y);
            ulonglong2 zw; zw.x = pk2(q0.z, q1.z); zw.y = pk2(q0.w, q1.w);
            s_xy[p] = xy; s_zw[p] = zw;
            s_lq[p] = pk2(g_lgR[j], g_lgR[j + 1]);
        }
        __syncthreads();
#pragma unroll 4
        for (int it = 0; it < TILE / 64; it++) {
            if (SPARSE) {
                int ci = (b * 64 + (c >> 6) + it) * 2;
                float4 clo = __ldg(&g_cb[1][ci]), chi = __ldg(&g_cb[1][ci + 1]);
                float gx = fmaxf(0.0f, fmaxf(clo.x - whx, wlx - chi.x));
                float gy = fmaxf(0.0f, fmaxf(clo.y - why, wly - chi.y));
                float gz = fmaxf(0.0f, fmaxf(clo.z - whz, wlz - chi.z));
                if (gx * gx + gy * gy + gz * gz > cut2) continue;
            }
            int p = it * 32 + lane;
            ulonglong2 xy = s_xy[p];
            ulonglong2 zw = s_zw[p];
            u64 lq2 = s_lq[p];
            u64 d0 = f2fma(rz[0], zw.x, f2fma(ry[0], xy.y, f2fma(rx[0], xy.x, f2add(zw.y, rw[0]))));
            u64 d1 = f2fma(rz[1], zw.x, f2fma(ry[1], xy.y, f2fma(rx[1], xy.x, f2add(zw.y, rw[1]))));
            u64 d2 = f2fma(rz[2], zw.x, f2fma(ry[2], xy.y, f2fma(rx[2], xy.x, f2add(zw.y, rw[2]))));
            u64 d3 = f2fma(rz[3], zw.x, f2fma(ry[3], xy.y, f2fma(rx[3], xy.x, f2add(zw.y, rw[3]))));
            u64 a0 = f2fma(klg2, d0, lq2);
            u64 a1 = f2fma(klg2, d1, lq2);
            u64 a2 = f2fma(klg2, d2, lq2);
            u64 a3 = f2fma(klg2, d3, lq2);
            float f0, f1, f2v, f3v, f4, f5, f6, f7;
            upk2(f0, f1, a0); upk2(f2v, f3v, a1); upk2(f4, f5, a2); upk2(f6, f7, a3);
            if (SPARSE) {
                float m0 = fmaxf(fmaxf(f0, f1), fmaxf(f2v, f3v));
                float m1 = fmaxf(fmaxf(f4, f5), fmaxf(f6, f7));
                if (__all_sync(0xffffffffu, fmaxf(m0, m1) < UF_TH)) continue;
            }
#pragma unroll
            for (int r = 0; r < 4; r++) {
                u64 dd = (r == 0) ? d0 : (r == 1) ? d1 : (r == 2) ? d2 : d3;
                float av0, av1;
                if (r == 0)      { av0 = f0;  av1 = f1; }
                else if (r == 1) { av0 = f2v; av1 = f3v; }
                else if (r == 2) { av0 = f4;  av1 = f5; }
                else             { av0 = f6;  av1 = f7; }
                float dl, dh; upk2(dl, dh, dd);
                float c0 = fmaxf(dl, 1e-20f), c1 = fmaxf(dh, 1e-20f);
                float w0 = ex2f(av0), w1 = ex2f(av1);
                float s0 = sqrtf_apx(c0), s1 = sqrtf_apx(c1);
                u64 wv = pk2(w0, w1);
                wa[r] = f2add(wa[r], wv);
                cs[r] = f2fma(wv, pk2(s0, s1), cs[r]);
            }
        }
        __syncthreads();
    }

#pragma unroll
    for (int off = 16; off; off >>= 1) {
#pragma unroll
        for (int r = 0; r < 4; r++) {
            wa[r] = f2add(wa[r], __shfl_down_sync(0xffffffffu, wa[r], off));
            cs[r] = f2add(cs[r], __shfl_down_sync(0xffffffffu, cs[r], off));
        }
    }
    if (lane == 0) {
        float cost = 0.0f;
#pragma unroll
        for (int r = 0; r < 4; r++) {
            int idx = base + r0 + r;
            float eL = ex2f(lgL[r]);
            float wl, wh; upk2(wl, wh, wa[r]);
            float cl, ch; upk2(cl, ch, cs[r]);
            g_rL[idx] = fmaxf(0.0f, g_rL[idx] - eL * (wl + wh));
            cost = fmaf(eL, cl + ch, cost);
        }
        atomicAdd(&g_cost, cost);
    }
}

// ---- level == 0 sweep (e == 1): exact O(N) prep + sqrt-only pairwise cost ----
__global__ void level0_prep(int N) {
    __shared__ float red[256];
    __shared__ float Tv, Uv;
    const int b = blockIdx.x, base = b * N, t = threadIdx.x;
    float ts = 0.0f, us = 0.0f;
    for (int i = t; i < N; i += 256) { ts += g_rR[base + i]; us += g_rL[base + i]; }
    red[t] = ts; __syncthreads();
    for (int o = 128; o; o >>= 1) { if (t < o) red[t] += red[t + o]; __syncthreads(); }
    if (t == 0) Tv = red[0];
    __syncthreads();
    red[t] = us; __syncthreads();
    for (int o = 128; o; o >>= 1) { if (t < o) red[t] += red[t + o]; __syncthreads(); }
    if (t == 0) Uv = red[0];
    __syncthreads();
    float scale = 1.0f / (EMD_EPS + Tv);
    float S = Uv * scale;
    for (int i = t; i < N; i += 256) {
        g_lgL[base + i] = g_rL[base + i] * scale;
        float rr   = g_rR[base + i];
        float sumr = rr * S;
        float cons = fminf(rr / (sumr + EMD_EPS), 1.0f);
        g_lgR[base + i] = cons * rr;
    }
}

__global__ void __launch_bounds__(128, 6) level0_cost(int N) {
    __shared__ ulonglong2 s_xy[TILE / 2];
    __shared__ ulonglong2 s_zw[TILE / 2];
    __shared__ u64        s_rr[TILE / 2];
    const int b = blockIdx.y, base = b * N;
    const int t = threadIdx.x, warp = t >> 5, lane = t & 31;
    const int r0 = blockIdx.x * RPB + warp * 4;

    u64 rx[4], ry[4], rz[4], rw[4], cs[4];
    float rl[4];
#pragma unroll
    for (int r = 0; r < 4; r++) {
        float4 A = g_p1[base + r0 + r];
        rx[r] = pk2(-2.0f * A.x, -2.0f * A.x);
        ry[r] = pk2(-2.0f * A.y, -2.0f * A.y);
        rz[r] = pk2(-2.0f * A.z, -2.0f * A.z);
        rw[r] = pk2(A.w, A.w);
        rl[r] = g_lgL[base + r0 + r];
        cs[r] = 0ull;
    }

    for (int c = 0; c < N; c += TILE) {
#pragma unroll
        for (int k = 0; k < TILE / 256; k++) {
            int p = t + k * 128;
            int j = base + c + 2 * p;
            float4 q0 = g_p2[j], q1 = g_p2[j + 1];
            ulonglong2 xy; xy.x = pk2(q0.x, q1.x); xy.y = pk2(q0.y, q1.y);
            ulonglong2 zw; zw.x = pk2(q0.z, q1.z); zw.y = pk2(q0.w, q1.w);
            s_xy[p] = xy; s_zw[p] = zw;
            s_rr[p] = pk2(g_lgR[j], g_lgR[j + 1]);
        }
        __syncthreads();
#pragma unroll 4
        for (int it = 0; it < TILE / 64; it++) {
            int p = it * 32 + lane;
            ulonglong2 xy = s_xy[p];
            ulonglong2 zw = s_zw[p];
            u64 rr2 = s_rr[p];
#pragma unroll
            for (int r = 0; r < 4; r++) {
                u64 dd = f2fma(rz[r], zw.x, f2fma(ry[r], xy.y, f2fma(rx[r], xy.x, f2add(zw.y, rw[r]))));
                float dl, dh; upk2(dl, dh, dd);
                float s0 = sqrtf_apx(fmaxf(dl, 1e-20f));
                float s1 = sqrtf_apx(fmaxf(dh, 1e-20f));
                cs[r] = f2fma(rr2, pk2(s0, s1), cs[r]);
            }
        }
        __syncthreads();
    }

#pragma unroll
    for (int off = 16; off; off >>= 1) {
#pragma unroll
        for (int r = 0; r < 4; r++)
            cs[r] = f2add(cs[r], __shfl_down_sync(0xffffffffu, cs[r], off));
    }
    if (lane == 0) {
        float cost = 0.0f;
#pragma unroll
        for (int r = 0; r < 4; r++) {
            float cl, ch; upk2(cl, ch, cs[r]);
            cost = fmaf(rl[r], cl + ch, cost);
        }
        atomicAdd(&g_cost, cost);
    }
}

__global__ void final_kernel(float* out, float inv) {
    out[0] = g_cost * inv;
}

extern "C" void kernel_launch(void* const* d_in, const int* in_sizes, int n_in,
                              void* d_out, int out_size) {
    const float* x1 = (const float*)d_in[0];
    const float* x2 = (const float*)d_in[1];
    const int B = NB;
    const int N = in_sizes[0] / (3 * B);   // 4096
    const int n = N, m = N;

    float multiL, multiR;
    if (n >= m) { multiL = 1.0f; multiR = (float)(n / m); }
    else        { multiL = (float)(m / n); multiR = 1.0f; }

    sort_kernel<<<dim3(B, 2), 512>>>(x1, x2, multiL, multiR, N);
    bbox_kernel<<<dim3(B, 2), 512>>>(N);

    dim3 grid(N / RPB, B);
    const float LOG2E = 1.4426950408889634f;
    for (int s = 0; s < 9; s++) {
        float level = -ldexpf(1.0f, 2 * (7 - s));   // -4^(7-s); s=8 -> -0.25
        float klg = level * LOG2E;
        if (s <= 5) {
            float cutA = 130.0f / (-klg);   // P1/P3: col fold <= 0
            float cutB = 160.0f / (-klg);   // P2: col fold lgL <= ~30
            pass12_kernel<1, true><<<grid, 128>>>(klg, cutA, N);
            pass12_kernel<2, true><<<grid, 128>>>(klg, cutB, N);
            pass3_kernel<true><<<grid, 128>>>(klg, cutA, N);
        } else {
            pass12_kernel<1, false><<<grid, 128>>>(klg, 0.0f, N);
            pass12_kernel<2, false><<<grid, 128>>>(klg, 0.0f, N);
            pass3_kernel<false><<<grid, 128>>>(klg, 0.0f, N);
        }
    }
    level0_prep<<<B, 256>>>(N);
    level0_cost<<<grid, 128>>>(N);

    float mn = (float)((n < m ? n : m) * B);
    final_kernel<<<1, 1>>>((float*)d_out, 1.0f / mn);
}

// round 5
// speedup vs baseline: 1.4356x; 1.4356x over previous
#include <cuda_runtime.h>
#include <math.h>

// EMD approxmatch (Fan et al.) on GB300 — round 5.
// R3 core (packed f32x2, arg-vote, exact level-0) + Morton sort + precomputed
// 64-bit chunk skip-masks (bbox underflow pruning), gated per sweep.
// B=4, N=4096.

#define EMD_EPS 1e-9f
#define NB 4
#define MAXBN (NB * 4096)
#define TILE 1024
#define RPB 16   // rows per block: 4 warps x 4 rows

typedef unsigned long long u64;

__device__ float4 g_p1[MAXBN];   // sorted (x,y,z,|p|^2) xyz1
__device__ float4 g_p2[MAXBN];   // sorted (x,y,z,|p|^2) xyz2
__device__ float  g_rL[MAXBN];
__device__ float  g_rR[MAXBN];
__device__ float  g_lgL[MAXBN];  // log2(ratioL)  (raw ratioL during level-0 sweep)
__device__ float  g_lgR[MAXBN];  // log2(ratioR)  (raw ratioR during level-0 sweep)
__device__ float  g_cost;
__device__ float4 g_cb[2][NB * 64 * 2];  // 64-pt chunk bboxes: [(b*64+c)*2 + {lo,hi}]

__device__ __forceinline__ float ex2f(float x) {
    float y; asm("ex2.approx.ftz.f32 %0, %1;" : "=f"(y) : "f"(x)); return y;
}
__device__ __forceinline__ float lg2f(float x) {
    float y; asm("lg2.approx.ftz.f32 %0, %1;" : "=f"(y) : "f"(x)); return y;
}
__device__ __forceinline__ float sqrtf_apx(float x) {
    float y; asm("sqrt.approx.ftz.f32 %0, %1;" : "=f"(y) : "f"(x)); return y;
}
__device__ __forceinline__ u64 pk2(float a, float b) {
    u64 r; asm("mov.b64 %0, {%1, %2};" : "=l"(r) : "f"(a), "f"(b)); return r;
}
__device__ __forceinline__ void upk2(float& a, float& b, u64 v) {
    asm("mov.b64 {%0, %1}, %2;" : "=f"(a), "=f"(b) : "l"(v));
}
__device__ __forceinline__ u64 f2fma(u64 a, u64 b, u64 c) {
    u64 d; asm("fma.rn.f32x2 %0, %1, %2, %3;" : "=l"(d) : "l"(a), "l"(b), "l"(c)); return d;
}
__device__ __forceinline__ u64 f2add(u64 a, u64 b) {
    u64 d; asm("add.rn.f32x2 %0, %1, %2;" : "=l"(d) : "l"(a), "l"(b)); return d;
}

#define UF_TH (-125.0f)

__device__ __forceinline__ unsigned mort1(unsigned v) {
    return (v & 1u) | ((v & 2u) << 2) | ((v & 4u) << 4);
}

// bbox gap test: 1 = chunk provably underflows for this warp's rows
__device__ __forceinline__ bool chunk_skip(const float4* CB, int ci,
                                           float wlx, float wly, float wlz,
                                           float whx, float why, float whz, float cut2) {
    float4 clo = __ldg(&CB[ci * 2]);
    float4 chi = __ldg(&CB[ci * 2 + 1]);
    float gx = fmaxf(0.0f, fmaxf(clo.x - whx, wlx - chi.x));
    float gy = fmaxf(0.0f, fmaxf(clo.y - why, wly - chi.y));
    float gz = fmaxf(0.0f, fmaxf(clo.z - whz, wlz - chi.z));
    return gx * gx + gy * gy + gz * gz > cut2;
}

// Counting sort by Morton cell id (8^3 cells over [-4,4]^3). grid (B,2), block 512.
__global__ void sort_kernel(const float* __restrict__ x1, const float* __restrict__ x2,
                            float multiL, float multiR, int N) {
    __shared__ unsigned hist[512];
    __shared__ unsigned scan[512];
    __shared__ unsigned offs[512];
    const int b = blockIdx.x, side = blockIdx.y, t = threadIdx.x;
    const float* px = (side ? x2 : x1) + (size_t)b * 3 * N;
    hist[t] = 0;
    __syncthreads();
    for (int i = t; i < N; i += 512) {
        float a = px[i], c = px[i + N], d = px[i + 2 * N];
        unsigned cx = (unsigned)min(7, max(0, (int)floorf(a + 4.0f)));
        unsigned cy = (unsigned)min(7, max(0, (int)floorf(c + 4.0f)));
        unsigned cz = (unsigned)min(7, max(0, (int)floorf(d + 4.0f)));
        unsigned cell = mort1(cx) | (mort1(cy) << 1) | (mort1(cz) << 2);
        atomicAdd(&hist[cell], 1u);
    }
    __syncthreads();
    scan[t] = hist[t];
    __syncthreads();
    for (int o = 1; o < 512; o <<= 1) {
        unsigned add = (t >= o) ? scan[t - o] : 0u;
        __syncthreads();
        scan[t] += add;
        __syncthreads();
    }
    offs[t] = scan[t] - hist[t];
    __syncthreads();
    for (int i = t; i < N; i += 512) {
        float a = px[i], c = px[i + N], d = px[i + 2 * N];
        unsigned cx = (unsigned)min(7, max(0, (int)floorf(a + 4.0f)));
        unsigned cy = (unsigned)min(7, max(0, (int)floorf(c + 4.0f)));
        unsigned cz = (unsigned)min(7, max(0, (int)floorf(d + 4.0f)));
        unsigned cell = mort1(cx) | (mort1(cy) << 1) | (mort1(cz) << 2);
        unsigned pos = atomicAdd(&offs[cell], 1u);
        int idx = b * N + (int)pos;
        float4 v = make_float4(a, c, d, a * a + c * c + d * d);
        if (side == 0) { g_p1[idx] = v; g_rL[idx] = multiL; }
        else           { g_p2[idx] = v; g_rR[idx] = multiR; }
    }
    if (b == 0 && side == 0 && t == 0) g_cost = 0.0f;
}

// Chunk (64-pt) bboxes from sorted arrays. grid (B,2), block 512.
__global__ void bbox_kernel(int N) {
    const int b = blockIdx.x, side = blockIdx.y, t = threadIdx.x;
    const int warp = t >> 5, lane = t & 31;
    const float4* P = side ? g_p2 : g_p1;
    float4* CB = g_cb[side];
    for (int c = warp; c < 64; c += 16) {
        int j = b * N + c * 64 + lane;
        float4 p0 = P[j], p1 = P[j + 32];
        float lx = fminf(p0.x, p1.x), hx = fmaxf(p0.x, p1.x);
        float ly = fminf(p0.y, p1.y), hy = fmaxf(p0.y, p1.y);
        float lz = fminf(p0.z, p1.z), hz = fmaxf(p0.z, p1.z);
#pragma unroll
        for (int o = 16; o; o >>= 1) {
            lx = fminf(lx, __shfl_xor_sync(0xffffffffu, lx, o));
            hx = fmaxf(hx, __shfl_xor_sync(0xffffffffu, hx, o));
            ly = fminf(ly, __shfl_xor_sync(0xffffffffu, ly, o));
            hy = fmaxf(hy, __shfl_xor_sync(0xffffffffu, hy, o));
            lz = fminf(lz, __shfl_xor_sync(0xffffffffu, lz, o));
            hz = fmaxf(hz, __shfl_xor_sync(0xffffffffu, hz, o));
        }
        if (lane == 0) {
            CB[(b * 64 + c) * 2]     = make_float4(lx, ly, lz, 0.0f);
            CB[(b * 64 + c) * 2 + 1] = make_float4(hx, hy, hz, 0.0f);
        }
    }
}

// MODE 1: rows = x1, cols = x2, fold_j = log2(remainR_j); epilogue writes lgL.
// MODE 2: rows = x2, cols = x1, fold_j = lgL_j;           epilogue updates remainR, writes lgR.
// PRUNE: 0 = dense, 1 = arg-vote only, 2 = chunk-mask + arg-vote.
template <int MODE, int PRUNE>
__global__ void __launch_bounds__(128, 6) pass12_kernel(float klg, float cut2, int N) {
    __shared__ ulonglong2 s_xy[TILE / 2];
    __shared__ ulonglong2 s_zf[TILE / 2];
    __shared__ unsigned s_bm[4][2];
    const int b = blockIdx.y, base = b * N;
    const int t = threadIdx.x, warp = t >> 5, lane = t & 31;
    const int r0 = blockIdx.x * RPB + warp * 4;

    const float4* P  = (MODE == 1) ? g_p1 : g_p2;
    const float4* Q  = (MODE == 1) ? g_p2 : g_p1;
    const float4* CB = (MODE == 1) ? g_cb[1] : g_cb[0];

    u64 rx[4], ry[4], rz[4], rw[4], acc[4];
    u64 wm = 0ull, bm = 0ull;   // skip masks (bit=1 -> skip chunk)
    {
        float4 A[4];
#pragma unroll
        for (int r = 0; r < 4; r++) A[r] = P[base + r0 + r];
#pragma unroll
        for (int r = 0; r < 4; r++) {
            float kx = klg * -2.0f * A[r].x, ky = klg * -2.0f * A[r].y, kz = klg * -2.0f * A[r].z;
            float kw = klg * A[r].w;
            rx[r] = pk2(kx, kx); ry[r] = pk2(ky, ky); rz[r] = pk2(kz, kz); rw[r] = pk2(kw, kw);
            acc[r] = 0ull;
        }
        if (PRUNE == 2) {
            float wlx = fminf(fminf(A[0].x, A[1].x), fminf(A[2].x, A[3].x));
            float whx = fmaxf(fmaxf(A[0].x, A[1].x), fmaxf(A[2].x, A[3].x));
            float wly = fminf(fminf(A[0].y, A[1].y), fminf(A[2].y, A[3].y));
            float why = fmaxf(fmaxf(A[0].y, A[1].y), fmaxf(A[2].y, A[3].y));
            float wlz = fminf(fminf(A[0].z, A[1].z), fminf(A[2].z, A[3].z));
            float whz = fmaxf(fmaxf(A[0].z, A[1].z), fmaxf(A[2].z, A[3].z));
            bool k0 = chunk_skip(CB, b * 64 + lane,      wlx, wly, wlz, whx, why, whz, cut2);
            bool k1 = chunk_skip(CB, b * 64 + lane + 32, wlx, wly, wlz, whx, why, whz, cut2);
            unsigned lo = __ballot_sync(0xffffffffu, k0);
            unsigned hi = __ballot_sync(0xffffffffu, k1);
            wm = ((u64)hi << 32) | lo;
            if (lane == 0) { s_bm[warp][0] = lo; s_bm[warp][1] = hi; }
            __syncthreads();
            unsigned blo = s_bm[0][0] & s_bm[1][0] & s_bm[2][0] & s_bm[3][0];
            unsigned bhi = s_bm[0][1] & s_bm[1][1] & s_bm[2][1] & s_bm[3][1];
            bm = ((u64)bhi << 32) | blo;
        }
    }

    for (int c = 0; c < N; c += TILE) {
        const int tb = c >> 6;   // first chunk index of this tile
        if (PRUNE == 2) {
            if ((unsigned)((bm >> tb) & 0xFFFFull) == 0xFFFFu) continue;   // block-uniform
        }
#pragma unroll
        for (int k = 0; k < TILE / 256; k++) {
            int p = t + k * 128;
            int j = base + c + 2 * p;
            float4 q0 = Q[j], q1 = Q[j + 1];
            float f0, f1;
            if (MODE == 1) { f0 = lg2f(g_rR[j]); f1 = lg2f(g_rR[j + 1]); }
            else           { f0 = g_lgL[j];      f1 = g_lgL[j + 1]; }
            f0 = fmaf(klg, q0.w, f0);
            f1 = fmaf(klg, q1.w, f1);
            ulonglong2 xy; xy.x = pk2(q0.x, q1.x); xy.y = pk2(q0.y, q1.y);
            ulonglong2 zf; zf.x = pk2(q0.z, q1.z); zf.y = pk2(f0, f1);
            s_xy[p] = xy; s_zf[p] = zf;
        }
        __syncthreads();
#pragma unroll 4
        for (int it = 0; it < TILE / 64; it++) {
            if (PRUNE == 2) {
                if ((wm >> (tb + it)) & 1ull) continue;   // warp-uniform, 2 ALU ops
            }
            int p = it * 32 + lane;
            ulonglong2 xy = s_xy[p];
            ulonglong2 zf = s_zf[p];
            u64 a0 = f2fma(rz[0], zf.x, f2fma(ry[0], xy.y, f2fma(rx[0], xy.x, f2add(zf.y, rw[0]))));
            u64 a1 = f2fma(rz[1], zf.x, f2fma(ry[1], xy.y, f2fma(rx[1], xy.x, f2add(zf.y, rw[1]))));
            u64 a2 = f2fma(rz[2], zf.x, f2fma(ry[2], xy.y, f2fma(rx[2], xy.x, f2add(zf.y, rw[2]))));
            u64 a3 = f2fma(rz[3], zf.x, f2fma(ry[3], xy.y, f2fma(rx[3], xy.x, f2add(zf.y, rw[3]))));
            float e0, e1, e2, e3, e4, e5, e6, e7;
            upk2(e0, e1, a0); upk2(e2, e3, a1); upk2(e4, e5, a2); upk2(e6, e7, a3);
            if (PRUNE >= 1) {
                float m0 = fmaxf(fmaxf(e0, e1), fmaxf(e2, e3));
                float m1 = fmaxf(fmaxf(e4, e5), fmaxf(e6, e7));
                if (__all_sync(0xffffffffu, fmaxf(m0, m1) < UF_TH)) continue;
            }
            acc[0] = f2add(acc[0], pk2(ex2f(e0), ex2f(e1)));
            acc[1] = f2add(acc[1], pk2(ex2f(e2), ex2f(e3)));
            acc[2] = f2add(acc[2], pk2(ex2f(e4), ex2f(e5)));
            acc[3] = f2add(acc[3], pk2(ex2f(e6), ex2f(e7)));
        }
        __syncthreads();
    }

#pragma unroll
    for (int off = 16; off; off >>= 1) {
#pragma unroll
        for (int r = 0; r < 4; r++)
            acc[r] = f2add(acc[r], __shfl_down_sync(0xffffffffu, acc[r], off));
    }
    if (lane == 0) {
#pragma unroll
        for (int r = 0; r < 4; r++) {
            float lo, hi; upk2(lo, hi, acc[r]);
            float a = lo + hi;
            int idx = base + r0 + r;
            if (MODE == 1) {
                g_lgL[idx] = lg2f(g_rL[idx] / (EMD_EPS + a));
            } else {
                float rr   = g_rR[idx];
                float sumr = rr * a;
                float cons = fminf(rr / (sumr + EMD_EPS), 1.0f);
                g_lgR[idx] = lg2f(cons * rr);
                g_rR[idx]  = fmaxf(0.0f, rr - sumr);
            }
        }
    }
}

// P3: w = ex2(klg*d + lq_j) * ex2(lgL_i); remainL -= sum_j w; cost += w*sqrt(max(d,1e-20))
template <int PRUNE>
__global__ void __launch_bounds__(128, 5) pass3_kernel(float klg, float cut2, int N) {
    __shared__ ulonglong2 s_xy[TILE / 2];
    __shared__ ulonglong2 s_zw[TILE / 2];
    __shared__ u64        s_lq[TILE / 2];
    __shared__ unsigned   s_bm[4][2];
    const int b = blockIdx.y, base = b * N;
    const int t = threadIdx.x, warp = t >> 5, lane = t & 31;
    const int r0 = blockIdx.x * RPB + warp * 4;

    u64 rx[4], ry[4], rz[4], rw[4], wa[4], cs[4];
    float lgL[4];
    u64 wm = 0ull, bm = 0ull;
    {
        float4 A[4];
#pragma unroll
        for (int r = 0; r < 4; r++) A[r] = g_p1[base + r0 + r];
#pragma unroll
        for (int r = 0; r < 4; r++) {
            rx[r] = pk2(-2.0f * A[r].x, -2.0f * A[r].x);
            ry[r] = pk2(-2.0f * A[r].y, -2.0f * A[r].y);
            rz[r] = pk2(-2.0f * A[r].z, -2.0f * A[r].z);
            rw[r] = pk2(A[r].w, A[r].w);
            lgL[r] = g_lgL[base + r0 + r];
            wa[r] = 0ull; cs[r] = 0ull;
        }
        if (PRUNE == 2) {
            float wlx = fminf(fminf(A[0].x, A[1].x), fminf(A[2].x, A[3].x));
            float whx = fmaxf(fmaxf(A[0].x, A[1].x), fmaxf(A[2].x, A[3].x));
            float wly = fminf(fminf(A[0].y, A[1].y), fminf(A[2].y, A[3].y));
            float why = fmaxf(fmaxf(A[0].y, A[1].y), fmaxf(A[2].y, A[3].y));
            float wlz = fminf(fminf(A[0].z, A[1].z), fminf(A[2].z, A[3].z));
            float whz = fmaxf(fmaxf(A[0].z, A[1].z), fmaxf(A[2].z, A[3].z));
            bool k0 = chunk_skip(g_cb[1], b * 64 + lane,      wlx, wly, wlz, whx, why, whz, cut2);
            bool k1 = chunk_skip(g_cb[1], b * 64 + lane + 32, wlx, wly, wlz, whx, why, whz, cut2);
            unsigned lo = __ballot_sync(0xffffffffu, k0);
            unsigned hi = __ballot_sync(0xffffffffu, k1);
            wm = ((u64)hi << 32) | lo;
            if (lane == 0) { s_bm[warp][0] = lo; s_bm[warp][1] = hi; }
            __syncthreads();
            unsigned blo = s_bm[0][0] & s_bm[1][0] & s_bm[2][0] & s_bm[3][0];
            unsigned bhi = s_bm[0][1] & s_bm[1][1] & s_bm[2][1] & s_bm[3][1];
            bm = ((u64)bhi << 32) | blo;
        }
    }
    const u64 klg2 = pk2(klg, klg);

    for (int c = 0; c < N; c += TILE) {
        const int tb = c >> 6;
        if (PRUNE == 2) {
            if ((unsigned)((bm >> tb) & 0xFFFFull) == 0xFFFFu) continue;
        }
#pragma unroll
        for (int k = 0; k < TILE / 256; k++) {
            int p = t + k * 128;
            int j = base + c + 2 * p;
            float4 q0 = g_p2[j], q1 = g_p2[j + 1];
            ulonglong2 xy; xy.x = pk2(q0.x, q1.x); xy.y = pk2(q0.y, q1.y);
            ulonglong2 zw; zw.x = pk2(q0.z, q1.z); zw.y = pk2(q0.w, q1.w);
            s_xy[p] = xy; s_zw[p] = zw;
            s_lq[p] = pk2(g_lgR[j], g_lgR[j + 1]);
        }
        __syncthreads();
#pragma unroll 4
        for (int it = 0; it < TILE / 64; it++) {
            if (PRUNE == 2) {
                if ((wm >> (tb + it)) & 1ull) continue;
            }
            int p = it * 32 + lane;
            ulonglong2 xy = s_xy[p];
            ulonglong2 zw = s_zw[p];
            u64 lq2 = s_lq[p];
            u64 d0 = f2fma(rz[0], zw.x, f2fma(ry[0], xy.y, f2fma(rx[0], xy.x, f2add(zw.y, rw[0]))));
            u64 d1 = f2fma(rz[1], zw.x, f2fma(ry[1], xy.y, f2fma(rx[1], xy.x, f2add(zw.y, rw[1]))));
            u64 d2 = f2fma(rz[2], zw.x, f2fma(ry[2], xy.y, f2fma(rx[2], xy.x, f2add(zw.y, rw[2]))));
            u64 d3 = f2fma(rz[3], zw.x, f2fma(ry[3], xy.y, f2fma(rx[3], xy.x, f2add(zw.y, rw[3]))));
            u64 a0 = f2fma(klg2, d0, lq2);
            u64 a1 = f2fma(klg2, d1, lq2);
            u64 a2 = f2fma(klg2, d2, lq2);
            u64 a3 = f2fma(klg2, d3, lq2);
            float f0, f1, f2v, f3v, f4, f5, f6, f7;
            upk2(f0, f1, a0); upk2(f2v, f3v, a1); upk2(f4, f5, a2); upk2(f6, f7, a3);
            if (PRUNE >= 1) {
                float m0 = fmaxf(fmaxf(f0, f1), fmaxf(f2v, f3v));
                float m1 = fmaxf(fmaxf(f4, f5), fmaxf(f6, f7));
                if (__all_sync(0xffffffffu, fmaxf(m0, m1) < UF_TH)) continue;
            }
#pragma unroll
            for (int r = 0; r < 4; r++) {
                u64 dd = (r == 0) ? d0 : (r == 1) ? d1 : (r == 2) ? d2 : d3;
                float av0, av1;
                if (r == 0)      { av0 = f0;  av1 = f1; }
                else if (r == 1) { av0 = f2v; av1 = f3v; }
                else if (r == 2) { av0 = f4;  av1 = f5; }
                else             { av0 = f6;  av1 = f7; }
                float dl, dh; upk2(dl, dh, dd);
                float c0 = fmaxf(dl, 1e-20f), c1 = fmaxf(dh, 1e-20f);
                float w0 = ex2f(av0), w1 = ex2f(av1);
                float s0 = sqrtf_apx(c0), s1 = sqrtf_apx(c1);
                u64 wv = pk2(w0, w1);
                wa[r] = f2add(wa[r], wv);
                cs[r] = f2fma(wv, pk2(s0, s1), cs[r]);
            }
        }
        __syncthreads();
    }

#pragma unroll
    for (int off = 16; off; off >>= 1) {
#pragma unroll
        for (int r = 0; r < 4; r++) {
            wa[r] = f2add(wa[r], __shfl_down_sync(0xffffffffu, wa[r], off));
            cs[r] = f2add(cs[r], __shfl_down_sync(0xffffffffu, cs[r], off));
        }
    }
    if (lane == 0) {
        float cost = 0.0f;
#pragma unroll
        for (int r = 0; r < 4; r++) {
            int idx = base + r0 + r;
            float eL = ex2f(lgL[r]);
            float wl, wh; upk2(wl, wh, wa[r]);
            float cl, ch; upk2(cl, ch, cs[r]);
            g_rL[idx] = fmaxf(0.0f, g_rL[idx] - eL * (wl + wh));
            cost = fmaf(eL, cl + ch, cost);
        }
        atomicAdd(&g_cost, cost);
    }
}

// ---- level == 0 sweep (e == 1): exact O(N) prep + sqrt-only pairwise cost ----
__global__ void level0_prep(int N) {
    __shared__ float red[256];
    __shared__ float Tv, Uv;
    const int b = blockIdx.x, base = b * N, t = threadIdx.x;
    float ts = 0.0f, us = 0.0f;
    for (int i = t; i < N; i += 256) { ts += g_rR[base + i]; us += g_rL[base + i]; }
    red[t] = ts; __syncthreads();
    for (int o = 128; o; o >>= 1) { if (t < o) red[t] += red[t + o]; __syncthreads(); }
    if (t == 0) Tv = red[0];
    __syncthreads();
    red[t] = us; __syncthreads();
    for (int o = 128; o; o >>= 1) { if (t < o) red[t] += red[t + o]; __syncthreads(); }
    if (t == 0) Uv = red[0];
    __syncthreads();
    float scale = 1.0f / (EMD_EPS + Tv);
    float S = Uv * scale;
    for (int i = t; i < N; i += 256) {
        g_lgL[base + i] = g_rL[base + i] * scale;     // raw ratioL
        float rr   = g_rR[base + i];
        float sumr = rr * S;
        float cons = fminf(rr / (sumr + EMD_EPS), 1.0f);
        g_lgR[base + i] = cons * rr;                  // raw ratioR
    }
}

__global__ void __launch_bounds__(128, 6) level0_cost(int N) {
    __shared__ ulonglong2 s_xy[TILE / 2];
    __shared__ ulonglong2 s_zw[TILE / 2];
    __shared__ u64        s_rr[TILE / 2];
    const int b = blockIdx.y, base = b * N;
    const int t = threadIdx.x, warp = t >> 5, lane = t & 31;
    const int r0 = blockIdx.x * RPB + warp * 4;

    u64 rx[4], ry[4], rz[4], rw[4], cs[4];
    float rl[4];
#pragma unroll
    for (int r = 0; r < 4; r++) {
        float4 A = g_p1[base + r0 + r];
        rx[r] = pk2(-2.0f * A.x, -2.0f * A.x);
        ry[r] = pk2(-2.0f * A.y, -2.0f * A.y);
        rz[r] = pk2(-2.0f * A.z, -2.0f * A.z);
        rw[r] = pk2(A.w, A.w);
        rl[r] = g_lgL[base + r0 + r];
        cs[r] = 0ull;
    }

    for (int c = 0; c < N; c += TILE) {
#pragma unroll
        for (int k = 0; k < TILE / 256; k++) {
            int p = t + k * 128;
            int j = base + c + 2 * p;
            float4 q0 = g_p2[j], q1 = g_p2[j + 1];
            ulonglong2 xy; xy.x = pk2(q0.x, q1.x); xy.y = pk2(q0.y, q1.y);
            ulonglong2 zw; zw.x = pk2(q0.z, q1.z); zw.y = pk2(q0.w, q1.w);
            s_xy[p] = xy; s_zw[p] = zw;
            s_rr[p] = pk2(g_lgR[j], g_lgR[j + 1]);
        }
        __syncthreads();
#pragma unroll 4
        for (int it = 0; it < TILE / 64; it++) {
            int p = it * 32 + lane;
            ulonglong2 xy = s_xy[p];
            ulonglong2 zw = s_zw[p];
            u64 rr2 = s_rr[p];
#pragma unroll
            for (int r = 0; r < 4; r++) {
                u64 dd = f2fma(rz[r], zw.x, f2fma(ry[r], xy.y, f2fma(rx[r], xy.x, f2add(zw.y, rw[r]))));
                float dl, dh; upk2(dl, dh, dd);
                float s0 = sqrtf_apx(fmaxf(dl, 1e-20f));
                float s1 = sqrtf_apx(fmaxf(dh, 1e-20f));
                cs[r] = f2fma(rr2, pk2(s0, s1), cs[r]);
            }
        }
        __syncthreads();
    }

#pragma unroll
    for (int off = 16; off; off >>= 1) {
#pragma unroll
        for (int r = 0; r < 4; r++)
            cs[r] = f2add(cs[r], __shfl_down_sync(0xffffffffu, cs[r], off));
    }
    if (lane == 0) {
        float cost = 0.0f;
#pragma unroll
        for (int r = 0; r < 4; r++) {
            float cl, ch; upk2(cl, ch, cs[r]);
            cost = fmaf(rl[r], cl + ch, cost);
        }
        atomicAdd(&g_cost, cost);
    }
}

__global__ void final_kernel(float* out, float inv) {
    out[0] = g_cost * inv;
}

extern "C" void kernel_launch(void* const* d_in, const int* in_sizes, int n_in,
                              void* d_out, int out_size) {
    const float* x1 = (const float*)d_in[0];
    const float* x2 = (const float*)d_in[1];
    const int B = NB;
    const int N = in_sizes[0] / (3 * B);   // 4096
    const int n = N, m = N;

    float multiL, multiR;
    if (n >= m) { multiL = 1.0f; multiR = (float)(n / m); }
    else        { multiL = (float)(m / n); multiR = 1.0f; }

    sort_kernel<<<dim3(B, 2), 512>>>(x1, x2, multiL, multiR, N);
    bbox_kernel<<<dim3(B, 2), 512>>>(N);

    dim3 grid(N / RPB, B);
    const float LOG2E = 1.4426950408889634f;
    for (int s = 0; s < 9; s++) {
        float level = -ldexpf(1.0f, 2 * (7 - s));   // -4^(7-s); s=8 -> -0.25
        float klg = level * LOG2E;
        float cutA = 130.0f / (-klg);   // P1/P3: col fold <= 0
        float cutB = 160.0f / (-klg);   // P2: col fold lgL <= ~30
        if (s <= 3) {            // chunk-mask + vote (cut radii 0.07..2.37)
            pass12_kernel<1, 2><<<grid, 128>>>(klg, cutA, N);
            pass12_kernel<2, 2><<<grid, 128>>>(klg, cutB, N);
            pass3_kernel<2><<<grid, 128>>>(klg, cutA, N);
        } else if (s == 4) {     // vote only
            pass12_kernel<1, 1><<<grid, 128>>>(klg, 0.0f, N);
            pass12_kernel<2, 1><<<grid, 128>>>(klg, 0.0f, N);
            pass3_kernel<1><<<grid, 128>>>(klg, 0.0f, N);
        } else {                 // fully dense
            pass12_kernel<1, 0><<<grid, 128>>>(klg, 0.0f, N);
            pass12_kernel<2, 0><<<grid, 128>>>(klg, 0.0f, N);
            pass3_kernel<0><<<grid, 128>>>(klg, 0.0f, N);
        }
    }
    level0_prep<<<B, 256>>>(N);
    level0_cost<<<grid, 128>>>(N);

    float mn = (float)((n < m ? n : m) * B);
    final_kernel<<<1, 1>>>((float*)d_out, 1.0f / mn);
}